// round 15
// baseline (speedup 1.0000x reference)
#include <cuda_runtime.h>
#include <stdint.h>

#define M_DIM 2048   // 8*256
#define N_DIM 1024   // out_features
#define K_DIM 1024   // in_features
#define KHALF 512

// Scratch (device globals; no allocation allowed)
__device__ float g_xf[K_DIM * M_DIM];  // decoded x, K-major: xf_t[k][m]
__device__ float g_wf[K_DIM * N_DIM];  // decoded w, K-major: wf_t[k][n]
__device__ float g_y0[M_DIM * N_DIM];  // s0 = chain k in [0,512)

// ---------------------------------------------------------------------------
// Decode FP8-E4M3 bit pulses -> fp32 (exact), writing K-major transposed.
// ---------------------------------------------------------------------------
__device__ __forceinline__ float decode_one(const float4* p)
{
    float4 a = p[0];
    float4 b = p[1];
    int s  = a.x > 0.5f;
    int ev = ((a.y > 0.5f) << 3) | ((a.z > 0.5f) << 2) |
             ((a.w > 0.5f) << 1) |  (b.x > 0.5f);
    int mv = ((b.y > 0.5f) << 2) | ((b.z > 0.5f) << 1) | (b.w > 0.5f);
    float frac = (float)mv * 0.125f;
    float mag;
    if (ev == 0) {
        mag = frac * 0.015625f;                     // frac * 2^-6 (exact)
    } else {
        float scale = __uint_as_float((unsigned)(ev + 120) << 23);  // 2^(ev-7)
        mag = (1.0f + frac) * scale;                // exact
    }
    return s ? -mag : mag;
}

#define XTILES ((M_DIM / 32) * (K_DIM / 32))   // 2048

__global__ void __launch_bounds__(256) decode_all_kernel(
    const float4* __restrict__ px, const float4* __restrict__ pw)
{
    __shared__ float tile[32][33];
    const int bid = blockIdx.x;
    const float4* p;
    float* out;
    int rows, m0, k0;
    if (bid < XTILES) {
        p = px; out = g_xf; rows = M_DIM;
        m0 = (bid / (K_DIM / 32)) * 32;
        k0 = (bid % (K_DIM / 32)) * 32;
    } else {
        p = pw; out = g_wf; rows = N_DIM;
        int b = bid - XTILES;
        m0 = (b / (K_DIM / 32)) * 32;
        k0 = (b % (K_DIM / 32)) * 32;
    }
    const int t = threadIdx.x;

#pragma unroll
    for (int r = 0; r < 4; r++) {
        int lin = t + r * 256;          // m-major
        int mm  = lin >> 5;
        int kk  = lin & 31;
        tile[kk][mm] = decode_one(p + 2 * ((size_t)(m0 + mm) * K_DIM + k0 + kk));
    }
    __syncthreads();
#pragma unroll
    for (int r = 0; r < 4; r++) {
        int lin = t + r * 256;          // k-major
        int kk  = lin >> 5;
        int mm  = lin & 31;
        out[(size_t)(k0 + kk) * rows + m0 + mm] = tile[kk][mm];
    }
}

// ---------------------------------------------------------------------------
// fp32 GEMM, split-K=2 reference order, two sequential launches:
//   HALF=0: g_y0 = flat ascending chain over k in [0,512)
//   HALF=1: s1 = chain over k in [512,1024); epilogue folds y = g_y0 + s1
//           (single fp32 add = reference rounding) and writes the 32 output
//           bit-pulses directly (fused encode).
// BM=128 x BN=64 tile, BK=16, 256 threads, 8x4 micro-tile, 4-stage cp.async.
// ---------------------------------------------------------------------------
#define BM 128
#define BN 64
#define BK 16
#define NHT (KHALF / BK)   // 32 tiles per half
#define PAD 4
#define SROWA (BM + PAD)
#define SROWB (BN + PAD)
#define STAGES 4

#define CP_ASYNC16(dst_u32, src_ptr) \
    asm volatile("cp.async.cg.shared.global [%0], [%1], 16;" \
                 :: "r"(dst_u32), "l"(src_ptr))
#define CP_COMMIT() asm volatile("cp.async.commit_group;")
#define CP_WAIT(n)  asm volatile("cp.async.wait_group %0;" :: "n"(n))

__device__ __forceinline__ uint32_t smem_u32(const void* p) {
    uint32_t a;
    asm("{ .reg .u64 t; cvta.to.shared.u64 t, %1; cvt.u32.u64 %0, t; }"
        : "=r"(a) : "l"(p));
    return a;
}

template<int HALF>
__global__ void __launch_bounds__(256, 3) gemm_kernel(uint4* __restrict__ pout)
{
    __shared__ float As[STAGES][BK][SROWA];
    __shared__ float Bs[STAGES][BK][SROWB];

    const int tid = threadIdx.x;
    const int tx  = tid & 15;   // n: 16 x 4
    const int ty  = tid >> 4;   // m: 16 x 8
    const int m0  = blockIdx.y * BM;
    const int n0  = blockIdx.x * BN;
    const int KOFF = HALF * KHALF;

    const int kA0 = tid >> 5,         pA0 = tid & 31;
    const int kA1 = (tid + 256) >> 5, pA1 = (tid + 256) & 31;
    const int kB  = tid >> 4,         pB  = tid & 15;

    const float* Asrc0 = &g_xf[(size_t)(KOFF + kA0) * M_DIM + m0 + pA0 * 4];
    const float* Asrc1 = &g_xf[(size_t)(KOFF + kA1) * M_DIM + m0 + pA1 * 4];
    const float* Bsrc  = &g_wf[(size_t)(KOFF + kB ) * N_DIM + n0 + pB  * 4];
    const size_t stepA = (size_t)BK * M_DIM;
    const size_t stepB = (size_t)BK * N_DIM;

    uint32_t dA0[STAGES], dA1[STAGES], dB[STAGES];
#pragma unroll
    for (int b = 0; b < STAGES; b++) {
        dA0[b] = smem_u32(&As[b][kA0][pA0 * 4]);
        dA1[b] = smem_u32(&As[b][kA1][pA1 * 4]);
        dB[b]  = smem_u32(&Bs[b][kB ][pB  * 4]);
    }

    float acc[8][4];
#pragma unroll
    for (int i = 0; i < 8; i++)
#pragma unroll
        for (int j = 0; j < 4; j++) acc[i][j] = 0.0f;

#pragma unroll
    for (int pt = 0; pt < 2; pt++) {
        CP_ASYNC16(dA0[pt], Asrc0 + pt * stepA);
        CP_ASYNC16(dA1[pt], Asrc1 + pt * stepA);
        CP_ASYNC16(dB[pt],  Bsrc  + pt * stepB);
        CP_COMMIT();
    }

    for (int kt = 0; kt < NHT; kt++) {
        const int buf = kt % STAGES;
        if (kt + 2 < NHT) {
            const int nb = (kt + 2) % STAGES;
            CP_ASYNC16(dA0[nb], Asrc0 + (size_t)(kt + 2) * stepA);
            CP_ASYNC16(dA1[nb], Asrc1 + (size_t)(kt + 2) * stepA);
            CP_ASYNC16(dB[nb],  Bsrc  + (size_t)(kt + 2) * stepB);
            CP_COMMIT();
            CP_WAIT(2);
        } else {
            CP_WAIT(0);
        }
        __syncthreads();

#pragma unroll
        for (int kk = 0; kk < BK; kk++) {
            float a[8], b[4];
            float4 a0 = *(const float4*)&As[buf][kk][ty * 8];
            float4 a1 = *(const float4*)&As[buf][kk][ty * 8 + 4];
            float4 b0 = *(const float4*)&Bs[buf][kk][tx * 4];
            a[0]=a0.x; a[1]=a0.y; a[2]=a0.z; a[3]=a0.w;
            a[4]=a1.x; a[5]=a1.y; a[6]=a1.z; a[7]=a1.w;
            b[0]=b0.x; b[1]=b0.y; b[2]=b0.z; b[3]=b0.w;
#pragma unroll
            for (int i = 0; i < 8; i++)
#pragma unroll
                for (int j = 0; j < 4; j++)
                    acc[i][j] = fmaf(a[i], b[j], acc[i][j]);
        }
    }

    if (HALF == 0) {
        // store s0
#pragma unroll
        for (int i = 0; i < 8; i++) {
            size_t base = (size_t)(m0 + ty * 8 + i) * N_DIM + n0 + tx * 4;
            *(float4*)&g_y0[base] = make_float4(acc[i][0], acc[i][1],
                                                acc[i][2], acc[i][3]);
        }
    } else {
        // fold y = s0 + s1 (reference rounding) and emit 32 pulses/element.
        const unsigned ONE = 0x3F800000u;
#pragma unroll
        for (int i = 0; i < 8; i++) {
            size_t ebase = (size_t)(m0 + ty * 8 + i) * N_DIM + n0 + tx * 4;
            float4 s0 = *(const float4*)&g_y0[ebase];
            float ys[4] = {s0.x + acc[i][0], s0.y + acc[i][1],
                           s0.z + acc[i][2], s0.w + acc[i][3]};
#pragma unroll
            for (int j = 0; j < 4; j++) {
                unsigned bits = __float_as_uint(ys[j]);
                uint4* o = pout + (ebase + j) * 8;   // 32 floats = 8 uint4
#pragma unroll
                for (int q = 0; q < 8; q++) {
                    int sh = 31 - q * 4;
                    uint4 v;
                    v.x = ((bits >> sh)       & 1u) * ONE;
                    v.y = ((bits >> (sh - 1)) & 1u) * ONE;
                    v.z = ((bits >> (sh - 2)) & 1u) * ONE;
                    v.w = ((bits >> (sh - 3)) & 1u) * ONE;
                    __stcs(&o[q], v);
                }
            }
        }
    }
}

// ---------------------------------------------------------------------------
extern "C" void kernel_launch(void* const* d_in, const int* in_sizes, int n_in,
                              void* d_out, int out_size)
{
    const float4* x = (const float4*)d_in[0];   // [8,256,1024,8]
    const float4* w = (const float4*)d_in[1];   // [1024,1024,8]

    const int wtiles = (N_DIM / 32) * (K_DIM / 32);   // 1024
    decode_all_kernel<<<XTILES + wtiles, 256>>>(x, w);

    dim3 ggrid(N_DIM / BN, M_DIM / BM);   // (16, 16) = 256 CTAs per half
    gemm_kernel<0><<<ggrid, 256>>>((uint4*)d_out);
    gemm_kernel<1><<<ggrid, 256>>>((uint4*)d_out);
}

// round 16
// speedup vs baseline: 1.3427x; 1.3427x over previous
#include <cuda_runtime.h>
#include <stdint.h>

#define M_DIM 2048   // 8*256
#define N_DIM 1024   // out_features
#define K_DIM 1024   // in_features
#define KHALF 512

// Scratch (device globals; no allocation allowed)
__device__ float g_xf[K_DIM * M_DIM];  // decoded x, K-major: xf_t[k][m]
__device__ float g_wf[K_DIM * N_DIM];  // decoded w, K-major: wf_t[k][n]
__device__ float g_y0[M_DIM * N_DIM];  // s0 = chain k in [0,512)
__device__ float g_y1[M_DIM * N_DIM];  // s1 = chain k in [512,1024)

// ---------------------------------------------------------------------------
// Decode FP8-E4M3 bit pulses -> fp32 (exact), writing K-major transposed.
// ---------------------------------------------------------------------------
__device__ __forceinline__ float decode_one(const float4* p)
{
    float4 a = p[0];
    float4 b = p[1];
    int s  = a.x > 0.5f;
    int ev = ((a.y > 0.5f) << 3) | ((a.z > 0.5f) << 2) |
             ((a.w > 0.5f) << 1) |  (b.x > 0.5f);
    int mv = ((b.y > 0.5f) << 2) | ((b.z > 0.5f) << 1) | (b.w > 0.5f);
    float frac = (float)mv * 0.125f;
    float mag;
    if (ev == 0) {
        mag = frac * 0.015625f;                     // frac * 2^-6 (exact)
    } else {
        float scale = __uint_as_float((unsigned)(ev + 120) << 23);  // 2^(ev-7)
        mag = (1.0f + frac) * scale;                // exact
    }
    return s ? -mag : mag;
}

#define XTILES ((M_DIM / 32) * (K_DIM / 32))   // 2048

__global__ void __launch_bounds__(256) decode_all_kernel(
    const float4* __restrict__ px, const float4* __restrict__ pw)
{
    __shared__ float tile[32][33];
    const int bid = blockIdx.x;
    const float4* p;
    float* out;
    int rows, m0, k0;
    if (bid < XTILES) {
        p = px; out = g_xf; rows = M_DIM;
        m0 = (bid / (K_DIM / 32)) * 32;
        k0 = (bid % (K_DIM / 32)) * 32;
    } else {
        p = pw; out = g_wf; rows = N_DIM;
        int b = bid - XTILES;
        m0 = (b / (K_DIM / 32)) * 32;
        k0 = (b % (K_DIM / 32)) * 32;
    }
    const int t = threadIdx.x;

#pragma unroll
    for (int r = 0; r < 4; r++) {
        int lin = t + r * 256;          // m-major
        int mm  = lin >> 5;
        int kk  = lin & 31;
        tile[kk][mm] = decode_one(p + 2 * ((size_t)(m0 + mm) * K_DIM + k0 + kk));
    }
    __syncthreads();
#pragma unroll
    for (int r = 0; r < 4; r++) {
        int lin = t + r * 256;          // k-major
        int kk  = lin >> 5;
        int mm  = lin & 31;
        out[(size_t)(k0 + kk) * rows + m0 + mm] = tile[kk][mm];
    }
}

// ---------------------------------------------------------------------------
// fp32 GEMM, split-K=2 reference order; blockIdx.z selects K half.
// Scalar FFMA, flat ascending chain per half. 128x128 tile, BK=16,
// 256 threads, 8x8 micro-tile (best LDS-bytes/FMA ratio: 1.0 B/FMA),
// 4-stage cp.async, one syncthreads per tile.
// ---------------------------------------------------------------------------
#define BM 128
#define BN 128
#define BK 16
#define NHT (KHALF / BK)   // 32 tiles per half
#define PAD 4
#define SROW (BM + PAD)    // 132 floats (528B rows, 16B aligned)
#define STAGES 4

#define CP_ASYNC16(dst_u32, src_ptr) \
    asm volatile("cp.async.cg.shared.global [%0], [%1], 16;" \
                 :: "r"(dst_u32), "l"(src_ptr))
#define CP_COMMIT() asm volatile("cp.async.commit_group;")
#define CP_WAIT(n)  asm volatile("cp.async.wait_group %0;" :: "n"(n))

__device__ __forceinline__ uint32_t smem_u32(const void* p) {
    uint32_t a;
    asm("{ .reg .u64 t; cvta.to.shared.u64 t, %1; cvt.u32.u64 %0, t; }"
        : "=r"(a) : "l"(p));
    return a;
}

__global__ void __launch_bounds__(256, 2) gemm_kernel()
{
    __shared__ float As[STAGES][BK][SROW];
    __shared__ float Bs[STAGES][BK][SROW];

    const int tid = threadIdx.x;
    const int tx  = tid & 15;
    const int ty  = tid >> 4;
    const int m0  = blockIdx.y * BM;
    const int n0  = blockIdx.x * BN;
    const int KOFF = blockIdx.z * KHALF;
    float* yout = blockIdx.z ? g_y1 : g_y0;

    const int kkA = tid >> 5,         posA = tid & 31;
    const int kkB = (tid + 256) >> 5, posB = (tid + 256) & 31;
    const float* Asrc0 = &g_xf[(size_t)(KOFF + kkA) * M_DIM + m0 + posA * 4];
    const float* Asrc1 = &g_xf[(size_t)(KOFF + kkB) * M_DIM + m0 + posB * 4];
    const float* Bsrc0 = &g_wf[(size_t)(KOFF + kkA) * N_DIM + n0 + posA * 4];
    const float* Bsrc1 = &g_wf[(size_t)(KOFF + kkB) * N_DIM + n0 + posB * 4];
    const size_t stepA = (size_t)BK * M_DIM;
    const size_t stepB = (size_t)BK * N_DIM;

    uint32_t dA0[STAGES], dA1[STAGES], dB0[STAGES], dB1[STAGES];
#pragma unroll
    for (int b = 0; b < STAGES; b++) {
        dA0[b] = smem_u32(&As[b][kkA][posA * 4]);
        dA1[b] = smem_u32(&As[b][kkB][posB * 4]);
        dB0[b] = smem_u32(&Bs[b][kkA][posA * 4]);
        dB1[b] = smem_u32(&Bs[b][kkB][posB * 4]);
    }

    float acc[8][8];
#pragma unroll
    for (int i = 0; i < 8; i++)
#pragma unroll
        for (int j = 0; j < 8; j++) acc[i][j] = 0.0f;

    // prologue: issue tiles 0 and 1 (stage = tile index)
#pragma unroll
    for (int pt = 0; pt < 2; pt++) {
        const size_t oA = (size_t)pt * stepA;
        const size_t oB = (size_t)pt * stepB;
        CP_ASYNC16(dA0[pt], Asrc0 + oA);
        CP_ASYNC16(dA1[pt], Asrc1 + oA);
        CP_ASYNC16(dB0[pt], Bsrc0 + oB);
        CP_ASYNC16(dB1[pt], Bsrc1 + oB);
        CP_COMMIT();
    }

    for (int kt = 0; kt < NHT; kt++) {
        const int buf = kt % STAGES;
        if (kt + 2 < NHT) {
            const int nb = (kt + 2) % STAGES;
            const size_t oA = (size_t)(kt + 2) * stepA;
            const size_t oB = (size_t)(kt + 2) * stepB;
            CP_ASYNC16(dA0[nb], Asrc0 + oA);
            CP_ASYNC16(dA1[nb], Asrc1 + oA);
            CP_ASYNC16(dB0[nb], Bsrc0 + oB);
            CP_ASYNC16(dB1[nb], Bsrc1 + oB);
            CP_COMMIT();
            CP_WAIT(2);
        } else {
            CP_WAIT(0);
        }
        __syncthreads();   // single barrier per tile

#pragma unroll
        for (int kk = 0; kk < BK; kk++) {
            float a[8], b[8];
            float4 a0 = *(const float4*)&As[buf][kk][ty * 8];
            float4 a1 = *(const float4*)&As[buf][kk][ty * 8 + 4];
            float4 b0 = *(const float4*)&Bs[buf][kk][tx * 8];
            float4 b1 = *(const float4*)&Bs[buf][kk][tx * 8 + 4];
            a[0]=a0.x; a[1]=a0.y; a[2]=a0.z; a[3]=a0.w;
            a[4]=a1.x; a[5]=a1.y; a[6]=a1.z; a[7]=a1.w;
            b[0]=b0.x; b[1]=b0.y; b[2]=b0.z; b[3]=b0.w;
            b[4]=b1.x; b[5]=b1.y; b[6]=b1.z; b[7]=b1.w;
#pragma unroll
            for (int i = 0; i < 8; i++)
#pragma unroll
                for (int j = 0; j < 8; j++)
                    acc[i][j] = fmaf(a[i], b[j], acc[i][j]);
        }
    }

#pragma unroll
    for (int i = 0; i < 8; i++) {
        size_t base = (size_t)(m0 + ty * 8 + i) * N_DIM + n0 + tx * 8;
        *(float4*)&yout[base]     = make_float4(acc[i][0], acc[i][1], acc[i][2], acc[i][3]);
        *(float4*)&yout[base + 4] = make_float4(acc[i][4], acc[i][5], acc[i][6], acc[i][7]);
    }
}

// ---------------------------------------------------------------------------
// Encode (s0 + s1) -> 32 bit pulses (MSB first). One thread per 4 bits
// (one uint4, fully coalesced). Integer-only pulse construction, plain
// stores (R7 evidence: plain st.global beat stcs on this stream).
// The single fp32 add IS the reference's split-K fold (same rounding).
// ---------------------------------------------------------------------------
__global__ void __launch_bounds__(256) encode_kernel(
    const float* __restrict__ y0, const float* __restrict__ y1,
    uint4* __restrict__ out, int n4)
{
    int i = blockIdx.x * blockDim.x + threadIdx.x;
    if (i >= n4) return;
    int e = i >> 3;
    int g = i & 7;
    unsigned bits = __float_as_uint(__ldg(&y0[e]) + __ldg(&y1[e]));
    int sh = 31 - g * 4;
    const unsigned ONE = 0x3F800000u;
    uint4 o;
    o.x = ((bits >> sh)       & 1u) * ONE;
    o.y = ((bits >> (sh - 1)) & 1u) * ONE;
    o.z = ((bits >> (sh - 2)) & 1u) * ONE;
    o.w = ((bits >> (sh - 3)) & 1u) * ONE;
    out[i] = o;
}

// ---------------------------------------------------------------------------
extern "C" void kernel_launch(void* const* d_in, const int* in_sizes, int n_in,
                              void* d_out, int out_size)
{
    const float4* x = (const float4*)d_in[0];   // [8,256,1024,8]
    const float4* w = (const float4*)d_in[1];   // [1024,1024,8]

    float* y0; cudaGetSymbolAddress((void**)&y0, g_y0);
    float* y1; cudaGetSymbolAddress((void**)&y1, g_y1);

    const int wtiles = (N_DIM / 32) * (K_DIM / 32);   // 1024
    decode_all_kernel<<<XTILES + wtiles, 256>>>(x, w);

    dim3 ggrid(N_DIM / BN, M_DIM / BM, 2);   // (8, 16, 2) = 256 CTAs
    gemm_kernel<<<ggrid, 256>>>();

    const int n4 = M_DIM * N_DIM * 8;        // 16.8M uint4 threads
    encode_kernel<<<(n4 + 255) / 256, 256>>>(y0, y1, (uint4*)d_out, n4);
}

// round 17
// speedup vs baseline: 1.4618x; 1.0887x over previous
#include <cuda_runtime.h>
#include <stdint.h>

#define M_DIM 2048   // 8*256
#define N_DIM 1024   // out_features
#define K_DIM 1024   // in_features
#define KHALF 512

// Scratch (device globals; no allocation allowed)
__device__ float g_xf[K_DIM * M_DIM];  // decoded x, K-major: xf_t[k][m]
__device__ float g_wf[K_DIM * N_DIM];  // decoded w, K-major: wf_t[k][n]
__device__ float g_y0[M_DIM * N_DIM];  // s0 = chain k in [0,512)
__device__ float g_y1[M_DIM * N_DIM];  // s1 = chain k in [512,1024)

// ---------------------------------------------------------------------------
// Decode FP8-E4M3 bit pulses -> fp32 (exact), writing K-major transposed.
// ---------------------------------------------------------------------------
__device__ __forceinline__ float decode_one(const float4* p)
{
    float4 a = p[0];
    float4 b = p[1];
    int s  = a.x > 0.5f;
    int ev = ((a.y > 0.5f) << 3) | ((a.z > 0.5f) << 2) |
             ((a.w > 0.5f) << 1) |  (b.x > 0.5f);
    int mv = ((b.y > 0.5f) << 2) | ((b.z > 0.5f) << 1) | (b.w > 0.5f);
    float frac = (float)mv * 0.125f;
    float mag;
    if (ev == 0) {
        mag = frac * 0.015625f;                     // frac * 2^-6 (exact)
    } else {
        float scale = __uint_as_float((unsigned)(ev + 120) << 23);  // 2^(ev-7)
        mag = (1.0f + frac) * scale;                // exact
    }
    return s ? -mag : mag;
}

#define XTILES ((M_DIM / 32) * (K_DIM / 32))   // 2048

__global__ void __launch_bounds__(256) decode_all_kernel(
    const float4* __restrict__ px, const float4* __restrict__ pw)
{
    __shared__ float tile[32][33];
    const int bid = blockIdx.x;
    const float4* p;
    float* out;
    int rows, m0, k0;
    if (bid < XTILES) {
        p = px; out = g_xf; rows = M_DIM;
        m0 = (bid / (K_DIM / 32)) * 32;
        k0 = (bid % (K_DIM / 32)) * 32;
    } else {
        p = pw; out = g_wf; rows = N_DIM;
        int b = bid - XTILES;
        m0 = (b / (K_DIM / 32)) * 32;
        k0 = (b % (K_DIM / 32)) * 32;
    }
    const int t = threadIdx.x;

#pragma unroll
    for (int r = 0; r < 4; r++) {
        int lin = t + r * 256;          // m-major
        int mm  = lin >> 5;
        int kk  = lin & 31;
        tile[kk][mm] = decode_one(p + 2 * ((size_t)(m0 + mm) * K_DIM + k0 + kk));
    }
    __syncthreads();
#pragma unroll
    for (int r = 0; r < 4; r++) {
        int lin = t + r * 256;          // k-major
        int kk  = lin >> 5;
        int mm  = lin & 31;
        out[(size_t)(k0 + kk) * rows + m0 + mm] = tile[kk][mm];
    }
}

// ---------------------------------------------------------------------------
// fp32 GEMM, split-K=2 reference order; blockIdx.z selects K half.
// Scalar FFMA, flat ascending chain per half. 128x128 tile, BK=16,
// 256 threads, 8x8 micro-tile, 4-stage cp.async, one syncthreads per tile.
// ---------------------------------------------------------------------------
#define BM 128
#define BN 128
#define BK 16
#define NHT (KHALF / BK)   // 32 tiles per half
#define PAD 4
#define SROW (BM + PAD)    // 132 floats (528B rows, 16B aligned)
#define STAGES 4

#define CP_ASYNC16(dst_u32, src_ptr) \
    asm volatile("cp.async.cg.shared.global [%0], [%1], 16;" \
                 :: "r"(dst_u32), "l"(src_ptr))
#define CP_COMMIT() asm volatile("cp.async.commit_group;")
#define CP_WAIT(n)  asm volatile("cp.async.wait_group %0;" :: "n"(n))

__device__ __forceinline__ uint32_t smem_u32(const void* p) {
    uint32_t a;
    asm("{ .reg .u64 t; cvta.to.shared.u64 t, %1; cvt.u32.u64 %0, t; }"
        : "=r"(a) : "l"(p));
    return a;
}

__global__ void __launch_bounds__(256, 2) gemm_kernel()
{
    __shared__ float As[STAGES][BK][SROW];
    __shared__ float Bs[STAGES][BK][SROW];

    const int tid = threadIdx.x;
    const int tx  = tid & 15;
    const int ty  = tid >> 4;
    const int m0  = blockIdx.y * BM;
    const int n0  = blockIdx.x * BN;
    const int KOFF = blockIdx.z * KHALF;
    float* yout = blockIdx.z ? g_y1 : g_y0;

    const int kkA = tid >> 5,         posA = tid & 31;
    const int kkB = (tid + 256) >> 5, posB = (tid + 256) & 31;
    const float* Asrc0 = &g_xf[(size_t)(KOFF + kkA) * M_DIM + m0 + posA * 4];
    const float* Asrc1 = &g_xf[(size_t)(KOFF + kkB) * M_DIM + m0 + posB * 4];
    const float* Bsrc0 = &g_wf[(size_t)(KOFF + kkA) * N_DIM + n0 + posA * 4];
    const float* Bsrc1 = &g_wf[(size_t)(KOFF + kkB) * N_DIM + n0 + posB * 4];
    const size_t stepA = (size_t)BK * M_DIM;
    const size_t stepB = (size_t)BK * N_DIM;

    uint32_t dA0[STAGES], dA1[STAGES], dB0[STAGES], dB1[STAGES];
#pragma unroll
    for (int b = 0; b < STAGES; b++) {
        dA0[b] = smem_u32(&As[b][kkA][posA * 4]);
        dA1[b] = smem_u32(&As[b][kkB][posB * 4]);
        dB0[b] = smem_u32(&Bs[b][kkA][posA * 4]);
        dB1[b] = smem_u32(&Bs[b][kkB][posB * 4]);
    }

    float acc[8][8];
#pragma unroll
    for (int i = 0; i < 8; i++)
#pragma unroll
        for (int j = 0; j < 8; j++) acc[i][j] = 0.0f;

    // prologue: issue tiles 0 and 1 (stage = tile index)
#pragma unroll
    for (int pt = 0; pt < 2; pt++) {
        const size_t oA = (size_t)pt * stepA;
        const size_t oB = (size_t)pt * stepB;
        CP_ASYNC16(dA0[pt], Asrc0 + oA);
        CP_ASYNC16(dA1[pt], Asrc1 + oA);
        CP_ASYNC16(dB0[pt], Bsrc0 + oB);
        CP_ASYNC16(dB1[pt], Bsrc1 + oB);
        CP_COMMIT();
    }

    for (int kt = 0; kt < NHT; kt++) {
        const int buf = kt % STAGES;
        if (kt + 2 < NHT) {
            const int nb = (kt + 2) % STAGES;
            const size_t oA = (size_t)(kt + 2) * stepA;
            const size_t oB = (size_t)(kt + 2) * stepB;
            CP_ASYNC16(dA0[nb], Asrc0 + oA);
            CP_ASYNC16(dA1[nb], Asrc1 + oA);
            CP_ASYNC16(dB0[nb], Bsrc0 + oB);
            CP_ASYNC16(dB1[nb], Bsrc1 + oB);
            CP_COMMIT();
            CP_WAIT(2);
        } else {
            CP_WAIT(0);
        }
        __syncthreads();   // single barrier per tile

#pragma unroll
        for (int kk = 0; kk < BK; kk++) {
            float a[8], b[8];
            float4 a0 = *(const float4*)&As[buf][kk][ty * 8];
            float4 a1 = *(const float4*)&As[buf][kk][ty * 8 + 4];
            float4 b0 = *(const float4*)&Bs[buf][kk][tx * 8];
            float4 b1 = *(const float4*)&Bs[buf][kk][tx * 8 + 4];
            a[0]=a0.x; a[1]=a0.y; a[2]=a0.z; a[3]=a0.w;
            a[4]=a1.x; a[5]=a1.y; a[6]=a1.z; a[7]=a1.w;
            b[0]=b0.x; b[1]=b0.y; b[2]=b0.z; b[3]=b0.w;
            b[4]=b1.x; b[5]=b1.y; b[6]=b1.z; b[7]=b1.w;
#pragma unroll
            for (int i = 0; i < 8; i++)
#pragma unroll
                for (int j = 0; j < 8; j++)
                    acc[i][j] = fmaf(a[i], b[j], acc[i][j]);
        }
    }

#pragma unroll
    for (int i = 0; i < 8; i++) {
        size_t base = (size_t)(m0 + ty * 8 + i) * N_DIM + n0 + tx * 8;
        *(float4*)&yout[base]     = make_float4(acc[i][0], acc[i][1], acc[i][2], acc[i][3]);
        *(float4*)&yout[base + 4] = make_float4(acc[i][4], acc[i][5], acc[i][6], acc[i][7]);
    }
}

// ---------------------------------------------------------------------------
// Encode (s0 + s1) -> 32 bit pulses (MSB first). One thread per 4 bits
// (one uint4, fully coalesced). Integer-only pulse construction, __stcs
// streaming stores (A/B verified: stcs is ~14us faster than plain stores).
// The single fp32 add IS the reference's split-K fold (same rounding).
// ---------------------------------------------------------------------------
__global__ void __launch_bounds__(256) encode_kernel(
    const float* __restrict__ y0, const float* __restrict__ y1,
    uint4* __restrict__ out, int n4)
{
    int i = blockIdx.x * blockDim.x + threadIdx.x;
    if (i >= n4) return;
    int e = i >> 3;
    int g = i & 7;
    unsigned bits = __float_as_uint(__ldg(&y0[e]) + __ldg(&y1[e]));
    int sh = 31 - g * 4;
    const unsigned ONE = 0x3F800000u;
    uint4 o;
    o.x = ((bits >> sh)       & 1u) * ONE;
    o.y = ((bits >> (sh - 1)) & 1u) * ONE;
    o.z = ((bits >> (sh - 2)) & 1u) * ONE;
    o.w = ((bits >> (sh - 3)) & 1u) * ONE;
    __stcs(&out[i], o);
}

// ---------------------------------------------------------------------------
extern "C" void kernel_launch(void* const* d_in, const int* in_sizes, int n_in,
                              void* d_out, int out_size)
{
    const float4* x = (const float4*)d_in[0];   // [8,256,1024,8]
    const float4* w = (const float4*)d_in[1];   // [1024,1024,8]

    float* y0; cudaGetSymbolAddress((void**)&y0, g_y0);
    float* y1; cudaGetSymbolAddress((void**)&y1, g_y1);

    const int wtiles = (N_DIM / 32) * (K_DIM / 32);   // 1024
    decode_all_kernel<<<XTILES + wtiles, 256>>>(x, w);

    dim3 ggrid(N_DIM / BN, M_DIM / BM, 2);   // (8, 16, 2) = 256 CTAs
    gemm_kernel<<<ggrid, 256>>>();

    const int n4 = M_DIM * N_DIM * 8;        // 16.8M uint4 threads
    encode_kernel<<<(n4 + 255) / 256, 256>>>(y0, y1, (uint4*)d_out, n4);
}